// round 13
// baseline (speedup 1.0000x reference)
#include <cuda_runtime.h>
#include <math.h>

#define Nn 8192
#define Dd 4
#define Ff 256
#define Hh 512
#define Aa 64
#define Ee (Nn*Dd)
#define G4 2048
#define NCTA 32    /* recurrence CTAs per direction */
#define NPROD 84   /* producer CTAs (rest of the chip) */
#define ZG 16      /* floats per z group slot (4 data + 12 pad = 64B stride) */
#define CPAD 32    /* ints per counter slot: own 128B line */
#define FPAD 32    /* ints per pre-ready flag slot */

// ---------------- device scratch (no cudaMalloc allowed) ----------------
__device__ float g_preF[(size_t)Ee*G4];           // edges @ Wih_f^T + b_f
__device__ float g_preB[(size_t)Ee*G4];           // edges @ Wih_b^T + b_b
__device__ float g_arcA[(size_t)Ee*Hh];           // fwd arc_h (== ef, edge layout)
__device__ float g_arcB[(size_t)Ee*Hh];           // bwd arc_h at [node][slot]
__device__ float g_z  [2][(size_t)Nn*64*ZG];      // z accumulators, v4 groups
__device__ float g_hid[(size_t)Ee*Hh];            // decoder hidden
__device__ int   g_cz[2][(size_t)Nn*CPAD];        // per-node step barriers
__device__ int   g_prdy[2][256*FPAD];             // pre row-block ready (16 tiles)

// ---------------- helpers ----------------
__device__ __forceinline__ int ld_acq(const int* p){
    int v; asm volatile("ld.acquire.gpu.b32 %0,[%1];":"=r"(v):"l"(p):"memory"); return v;
}
__device__ __forceinline__ void red_rel(int* p){
    asm volatile("red.release.gpu.global.add.s32 [%0], 1;"::"l"(p):"memory");
}
__device__ __forceinline__ void red_v4(float* p, float a, float b, float c, float d){
    asm volatile("red.global.v4.f32.add [%0], {%1, %2, %3, %4};"
                 ::"l"(p),"f"(a),"f"(b),"f"(c),"f"(d):"memory");
}
__device__ __forceinline__ float fsig(float x){ return 1.f/(1.f+__expf(-x)); }
__device__ __forceinline__ float ftanh(float x){
    float e = __expf(-2.f*fabsf(x));
    float t = (1.f-e)/(1.f+e);
    return copysignf(t, x);
}
__device__ __forceinline__ void ffma2(unsigned long long& acc,
                                      unsigned long long a, unsigned long long b){
    asm("fma.rn.f32x2 %0, %1, %2, %0;" : "+l"(acc) : "l"(a), "l"(b));
}

// z slot address: node i, arc d, unit a  ->  i*1024 + (d*16 + a/4)*ZG + (a%4)
__device__ __forceinline__ size_t zaddr(int i, int d, int a){
    return (size_t)i*(64*ZG) + (size_t)(d*16 + (a>>2))*ZG + (a&3);
}

// ---------------- init: counters + z-seed (ba + x[:3] @ Wa[:,512:515]^T) ---
__global__ void init_kernel(const float* __restrict__ edges,
                            const float* __restrict__ Wa,
                            const float* __restrict__ ba)
{
    int idx = blockIdx.x*256 + threadIdx.x;        // 0 .. 2^22-1
    if (idx < Nn*CPAD){
        g_cz[0][idx]=0; g_cz[1][idx]=0;
    }
    if (idx < 256*FPAD){
        g_prdy[0][idx]=0; g_prdy[1][idx]=0;
    }
    int dir = idx >> 21;
    int rem = idx & ((1<<21)-1);
    int i = rem >> 8;
    int d = (rem >> 6) & 3;
    int a = rem & 63;
    float z = ba[a];
    size_t e = 0; bool ok = true;
    if (dir == 0) e = (size_t)i*4 + d;
    else { int cn = i+1+d; if (cn < Nn) e = (size_t)cn*4 + d; else ok = false; }
    if (ok){
        const float* x  = edges + e*Ff;
        const float* wr = Wa + (size_t)a*(Hh+3) + Hh;
        z += x[0]*wr[0] + x[1]*wr[1] + x[2]*wr[2];
    }
    g_z[dir][zaddr(i, d, a)] = z;
}

// ------------- decoder SGEMM (mode 1): A rows gathered [ef|eb] -------------
__global__ void __launch_bounds__(256) gemm_kernel(
    const float* __restrict__ B,
    const float* __restrict__ bias, float* __restrict__ C,
    int M, int Nc, int K)
{
    __shared__ float sA[16][132];
    __shared__ float sB[16][132];
    int tid = threadIdx.x;
    int n0 = blockIdx.x * 128;
    int m0 = blockIdx.y * 128;
    int tx = tid & 15, ty = tid >> 4;
    float acc[8][8];
    #pragma unroll
    for (int ii=0; ii<8; ii++)
        #pragma unroll
        for (int jj=0; jj<8; jj++) acc[ii][jj] = 0.f;

    for (int k0 = 0; k0 < K; k0 += 16){
        #pragma unroll
        for (int u = 0; u < 2; u++){
            int v = tid + u*256;
            int row = v >> 2, kq = v & 3;
            float4 va;
            {
                int e = m0 + row;
                int kk = k0 + kq*4;
                if (kk < Hh){
                    va = *(const float4*)(g_arcA + (size_t)e*Hh + kk);
                } else {
                    int d = e & 3, j = e >> 2;
                    if (j >= 1+d)
                        va = *(const float4*)(g_arcB + (size_t)(e - 4*(1+d))*Hh + (kk - Hh));
                    else
                        va = make_float4(0.f,0.f,0.f,0.f);
                }
            }
            sA[kq*4+0][row]=va.x; sA[kq*4+1][row]=va.y;
            sA[kq*4+2][row]=va.z; sA[kq*4+3][row]=va.w;
            float4 vb = *(const float4*)(B + (size_t)(n0+row)*K + k0 + kq*4);
            sB[kq*4+0][row]=vb.x; sB[kq*4+1][row]=vb.y;
            sB[kq*4+2][row]=vb.z; sB[kq*4+3][row]=vb.w;
        }
        __syncthreads();
        #pragma unroll
        for (int k=0; k<16; k++){
            float4 a0 = *(const float4*)&sA[k][ty*8];
            float4 a1 = *(const float4*)&sA[k][ty*8+4];
            float4 b0 = *(const float4*)&sB[k][tx*8];
            float4 b1 = *(const float4*)&sB[k][tx*8+4];
            float av[8] = {a0.x,a0.y,a0.z,a0.w,a1.x,a1.y,a1.z,a1.w};
            float bv[8] = {b0.x,b0.y,b0.z,b0.w,b1.x,b1.y,b1.z,b1.w};
            #pragma unroll
            for (int ii=0; ii<8; ii++)
                #pragma unroll
                for (int jj=0; jj<8; jj++)
                    acc[ii][jj] = fmaf(av[ii], bv[jj], acc[ii][jj]);
        }
        __syncthreads();
    }
    #pragma unroll
    for (int ii=0; ii<8; ii++){
        int m = m0 + ty*8 + ii;
        #pragma unroll
        for (int jj=0; jj<8; jj++){
            int n = n0 + tx*8 + jj;
            C[(size_t)m*Nc + n] = fmaxf(acc[ii][jj] + bias[n], 0.f);
        }
    }
}

// ---------------- producer body: pre = edges @ Wih^T + b, tiled ------------
// 8192 tiles (2 dirs x 256 rowblocks x 16 coltiles). fwd ascending, bwd
// descending rowblocks. Each tile RED+1s its rowblock flag (full at 16).
__device__ void producer_body(int gp,
    const float* __restrict__ edges,
    const float* __restrict__ Wih_f, const float* __restrict__ b_f,
    const float* __restrict__ Wih_b, const float* __restrict__ b_b)
{
    __shared__ float pA[16][132];
    __shared__ float pB[16][132];
    const int tid = threadIdx.x;
    const int tx = tid & 31, ty = tid >> 5;
    for (int tile = gp; tile < 8192; tile += NPROD){
        int dirp = tile & 1;
        int idx  = tile >> 1;
        int colT = idx & 15;
        int rb   = idx >> 4;
        int rowblk = dirp ? (255 - rb) : rb;
        const float* W  = dirp ? Wih_b : Wih_f;
        const float* bi = dirp ? b_b : b_f;
        float* C = dirp ? g_preB : g_preF;
        int m0 = rowblk * 128;
        int n0 = colT * 128;
        float acc[8][4];
        #pragma unroll
        for (int ii=0; ii<8; ii++)
            #pragma unroll
            for (int jj=0; jj<4; jj++) acc[ii][jj] = 0.f;

        for (int k0 = 0; k0 < Ff; k0 += 16){
            int row = tid >> 2, kq = tid & 3;
            float4 va = *(const float4*)(edges + (size_t)(m0+row)*Ff + k0 + kq*4);
            pA[kq*4+0][row]=va.x; pA[kq*4+1][row]=va.y;
            pA[kq*4+2][row]=va.z; pA[kq*4+3][row]=va.w;
            float4 vb = *(const float4*)(W + (size_t)(n0+row)*Ff + k0 + kq*4);
            pB[kq*4+0][row]=vb.x; pB[kq*4+1][row]=vb.y;
            pB[kq*4+2][row]=vb.z; pB[kq*4+3][row]=vb.w;
            __syncthreads();
            #pragma unroll
            for (int k=0; k<16; k++){
                float4 a0 = *(const float4*)&pA[k][ty*8];
                float4 a1 = *(const float4*)&pA[k][ty*8+4];
                float4 b0 = *(const float4*)&pB[k][tx*4];
                float av[8] = {a0.x,a0.y,a0.z,a0.w,a1.x,a1.y,a1.z,a1.w};
                float bv[4] = {b0.x,b0.y,b0.z,b0.w};
                #pragma unroll
                for (int ii=0; ii<8; ii++)
                    #pragma unroll
                    for (int jj=0; jj<4; jj++)
                        acc[ii][jj] = fmaf(av[ii], bv[jj], acc[ii][jj]);
            }
            __syncthreads();
        }
        #pragma unroll
        for (int ii=0; ii<8; ii++){
            int m = m0 + ty*8 + ii;
            #pragma unroll
            for (int jj=0; jj<4; jj++){
                int n = n0 + tx*4 + jj;
                __stcg(&C[(size_t)m*G4 + n], acc[ii][jj] + __ldg(bi + n));
            }
        }
        __threadfence();
        __syncthreads();
        if (tid == 0) red_rel(&g_prdy[dirp][rowblk*FPAD]);
    }
}

// ---------------- recurrence body (R11 structure + pre gating) -------------
__device__ void recur_body(int blk,
    const float* __restrict__ Whh_f, const float* __restrict__ Whh_b,
    const float* __restrict__ Wa, const float* __restrict__ Wao,
    const float* __restrict__ bao)
{
    const int dir = blk >> 5;
    const int ct  = blk & 31;
    const int tid = threadIdx.x;
    const int w = tid >> 5, l = tid & 31;

    const float* Whh = dir ? Whh_b : Whh_f;
    const float* preX = dir ? g_preB : g_preF;
    float* arc  = dir ? g_arcB : g_arcA;
    float* zArr = g_z[dir];
    int* cz = g_cz[dir];
    int* prdy = g_prdy[dir];

    __shared__ float sWa[16][64];
    __shared__ float sWao[64];
    __shared__ float sbao;
    __shared__ float h_s[4][16];
    __shared__ float carc_s[4][16];
    __shared__ float logit_s[4];
    __shared__ __align__(16) float hn_s[512];
    __shared__ float u_ring[4][64];   // [node&3][g*16+q]
    __shared__ float c_ring[4][16];   // [node&3][q]

    for (int x = tid; x < 16*64; x += 512){
        int q = x >> 6, a = x & 63;
        sWa[q][a] = Wa[(size_t)a*(Hh+3) + ct*16 + q];
    }
    if (tid < 64) sWao[tid] = Wao[tid];
    if (tid == 0) sbao = bao[0];

    // weights: thread -> local row r=tid>>3 (gate g=r>>4, dim q=r&15),
    // column quads (m*8+sub)*4, m=0..15 (conflict-free LDS.128 interleave)
    const int r   = tid >> 3;
    const int sub = tid & 7;
    const int rowG = (r >> 4)*Hh + ct*16 + (r & 15);
    ulonglong2 wq[16];
    #pragma unroll
    for (int m=0; m<16; m++){
        float4 v = *(const float4*)(Whh + (size_t)rowG*Hh + (m*8 + sub)*4);
        wq[m] = *(ulonglong2*)&v;
    }
    __syncthreads();

    // cell mapping (threads 0..63): arc dA, dim qA
    const int dA = tid >> 4, qA = tid & 15;
    const int jj = ct*16 + qA;

    // pre-ready trackers (per-thread, threads 0..63 only use them)
    int rdyHi = -1;    // fwd: highest confirmed rowblk
    int rdyLo = 256;   // bwd: lowest confirmed rowblk

    // t=0 prefetch: both ends have all arcs invalid -> zeros, no pre read
    float pg[4] = {0.f,0.f,0.f,0.f};

    for (int t = 0; t < Nn; t++){
        const int i = dir ? (Nn-1-t) : t;

        // ---- Phase A: cell (threads 0..63); u/c from local smem ring ----
        if (tid < 64){
            bool valid = dir ? (i+1+dA < Nn) : (i-1-dA >= 0);
            float ha = 0.f, ca = 0.f;
            if (valid){
                int p  = dir ? (i+1+dA) : (i-1-dA);
                int ps = p & 3;
                float gi = pg[0] + u_ring[ps][qA];
                float gf = pg[1] + u_ring[ps][16 + qA];
                float gg = pg[2] + u_ring[ps][32 + qA];
                float go = pg[3] + u_ring[ps][48 + qA];
                float cp = c_ring[ps][qA];
                ca = fsig(gf)*cp + fsig(gi)*ftanh(gg);
                ha = fsig(go)*ftanh(ca);
            }
            h_s[dA][qA] = ha; carc_s[dA][qA] = ca;
            __stcg(arc + ((size_t)i*4 + dA)*Hh + jj, ha);
        }
        __syncthreads();

        // ---- z partials (threads 0..255): slot tid = d*64+a, v4 REDs ---
        if (tid < 256){
            int d = tid >> 6, a = tid & 63;
            float v = 0.f;
            #pragma unroll
            for (int q=0; q<16; q++) v = fmaf(sWa[q][a], h_s[d][q], v);
            float v1 = __shfl_down_sync(0xffffffffu, v, 1);
            float v2 = __shfl_down_sync(0xffffffffu, v, 2);
            float v3 = __shfl_down_sync(0xffffffffu, v, 3);
            if ((tid & 3) == 0)
                red_v4(&zArr[(size_t)i*(64*ZG) + (size_t)(tid>>2)*ZG], v, v1, v2, v3);
        }
        __syncthreads();

        // ---- RELEASE FIRST (publish this CTA's arrival ASAP) ------------
        if (tid == 0) red_rel(&cz[(size_t)i*CPAD]);

        // ---- prefetch next step's pre (hidden under the barrier) -------
        if (tid < 64){
            pg[0]=pg[1]=pg[2]=pg[3]=0.f;
            if (t+1 < Nn){
                int i2 = dir ? (i-1) : (i+1);
                bool v2 = dir ? (i2+1+dA < Nn) : (i2-1-dA >= 0);
                if (v2){
                    int node = dir ? (i2+1+dA) : i2;
                    int nb = node >> 5;
                    if (dir == 0){
                        if (nb > rdyHi){
                            while (ld_acq(&prdy[nb*FPAD]) < 16) {}
                            rdyHi = nb;
                        }
                    } else {
                        if (nb < rdyLo){
                            while (ld_acq(&prdy[nb*FPAD]) < 16) {}
                            rdyLo = nb;
                        }
                    }
                    size_t e = dir ? ((size_t)node*4 + dA) : ((size_t)i2*4 + dA);
                    const float* pr = preX + e*G4;
                    pg[0]=__ldg(pr+jj); pg[1]=__ldg(pr+Hh+jj);
                    pg[2]=__ldg(pr+2*Hh+jj); pg[3]=__ldg(pr+3*Hh+jj);
                }
            }
        }
        if (tid == 0){
            while (ld_acq(&cz[(size_t)i*CPAD]) < NCTA) {}
        }
        __syncthreads();

        // ---- arc loads FIRST (independent), then logits (dependent) ----
        float av[4];
        #pragma unroll
        for (int d=0; d<4; d++)
            av[d] = __ldcg(arc + ((size_t)i*4 + d)*Hh + tid);
        if (w < 4){
            float z1 = __ldcg(&zArr[zaddr(i, w, l)]);
            float z2 = __ldcg(&zArr[zaddr(i, w, l + 32)]);
            float s = fmaxf(z1, 0.f)*sWao[l] + fmaxf(z2, 0.f)*sWao[l + 32];
            #pragma unroll
            for (int off=16; off; off >>= 1) s += __shfl_xor_sync(0xffffffffu, s, off);
            if (l == 0) logit_s[w] = ftanh(s + sbao);
        }
        __syncthreads();

        // ---- softmax weights (redundant per thread) ---------------------
        float wgt[4];
        {
            bool vld[4]; float m = -1e30f; int nv = 0;
            #pragma unroll
            for (int d=0; d<4; d++){
                vld[d] = dir ? (i+1+d < Nn) : (i-1-d >= 0);
                if (vld[d]){ m = fmaxf(m, logit_s[d]); nv++; }
            }
            float ssum = 0.f;
            #pragma unroll
            for (int d=0; d<4; d++){
                float ev = vld[d] ? __expf(logit_s[d]-m) : 0.f;
                wgt[d] = ev; ssum += ev;
            }
            if (nv){
                float inv = 1.f/ssum;
                #pragma unroll
                for (int d=0; d<4; d++) wgt[d] *= inv;
            }
        }

        // ---- h_node into smem; c_node into local ring -------------------
        {
            float h0 = 0.f;
            #pragma unroll
            for (int d=0; d<4; d++) h0 = fmaf(wgt[d], av[d], h0);
            hn_s[tid] = h0;
        }
        if (tid < 16){
            float c = 0.f;
            #pragma unroll
            for (int d=0; d<4; d++) c = fmaf(wgt[d], carc_s[d][tid], c);
            c_ring[i & 3][tid] = c;
        }
        __syncthreads();

        // ---- u rows = Whh_rows @ h_node, f32x2 + LDS.128 ----------------
        {
            unsigned long long acc0 = 0ull, acc1 = 0ull;
            const ulonglong2* hv4 = (const ulonglong2*)hn_s;
            #pragma unroll
            for (int m=0; m<16; m++){
                ulonglong2 hq = hv4[m*8 + sub];
                ffma2(acc0, wq[m].x, hq.x);
                ffma2(acc1, wq[m].y, hq.y);
            }
            float s = __uint_as_float((unsigned)acc0)
                    + __uint_as_float((unsigned)(acc0 >> 32))
                    + __uint_as_float((unsigned)acc1)
                    + __uint_as_float((unsigned)(acc1 >> 32));
            s += __shfl_xor_sync(0xffffffffu, s, 1);
            s += __shfl_xor_sync(0xffffffffu, s, 2);
            s += __shfl_xor_sync(0xffffffffu, s, 4);
            if (sub == 0) u_ring[i & 3][r] = s;
        }
        __syncthreads();   // ring visible before next step's cell
    }
}

// ---------------- fused kernel: 64 recurrence + 84 producer blocks ---------
__global__ void __launch_bounds__(512, 1) fused_kernel(
    const float* __restrict__ edges,
    const float* __restrict__ Wih_f, const float* __restrict__ b_f,
    const float* __restrict__ Wih_b, const float* __restrict__ b_b,
    const float* __restrict__ Whh_f, const float* __restrict__ Whh_b,
    const float* __restrict__ Wa, const float* __restrict__ Wao,
    const float* __restrict__ bao)
{
    if (blockIdx.x < 64)
        recur_body(blockIdx.x, Whh_f, Whh_b, Wa, Wao, bao);
    else
        producer_body(blockIdx.x - 64, edges, Wih_f, b_f, Wih_b, b_b);
}

// ---------------- final: out[e] = hid[e] . Wdo + bdo --------------------
__global__ void final_kernel(const float* __restrict__ Wdo,
                             const float* __restrict__ bdo,
                             float* __restrict__ out)
{
    int gw = (blockIdx.x*blockDim.x + threadIdx.x) >> 5;
    int l = threadIdx.x & 31;
    if (gw >= Ee) return;
    const float* h = g_hid + (size_t)gw*Hh;
    float s = 0.f;
    #pragma unroll
    for (int q=0; q<16; q++) s = fmaf(h[l + q*32], Wdo[l + q*32], s);
    #pragma unroll
    for (int off=16; off; off >>= 1) s += __shfl_xor_sync(0xffffffffu, s, off);
    if (l == 0) out[gw] = s + bdo[0];
}

// ---------------- launch --------------------------------------------------
extern "C" void kernel_launch(void* const* d_in, const int* in_sizes, int n_in,
                              void* d_out, int out_size)
{
    const float* edges = (const float*)d_in[0];
    const float* Wih_f = (const float*)d_in[1];
    const float* Whh_f = (const float*)d_in[2];
    const float* b_f   = (const float*)d_in[3];
    const float* Wih_b = (const float*)d_in[4];
    const float* Whh_b = (const float*)d_in[5];
    const float* b_b   = (const float*)d_in[6];
    const float* Wa    = (const float*)d_in[7];
    const float* ba    = (const float*)d_in[8];
    const float* Wao   = (const float*)d_in[9];
    const float* bao   = (const float*)d_in[10];
    const float* Wd    = (const float*)d_in[11];
    const float* bd    = (const float*)d_in[12];
    const float* Wdo   = (const float*)d_in[13];
    const float* bdo   = (const float*)d_in[14];
    float* out = (float*)d_out;

    float *hid;
    cudaGetSymbolAddress((void**)&hid, g_hid);

    // 1. counters + flags + z seed
    init_kernel<<<16384, 256>>>(edges, Wa, ba);
    // 2. fused: pre-GEMM producers overlapped with bidirectional recurrence
    fused_kernel<<<64 + NPROD, 512>>>(edges, Wih_f, b_f, Wih_b, b_b,
                                      Whh_f, Whh_b, Wa, Wao, bao);
    // 3. decoder GEMM: hid = relu(feat @ Wd^T + bd), feat gathered from arcs
    gemm_kernel<<<dim3(Hh/128, Ee/128), 256>>>(Wd, bd, hid, Ee, Hh, 2*Hh);
    // 4. output projection
    final_kernel<<<(Ee*32)/256, 256>>>(Wdo, bdo, out);
}

// round 15
// speedup vs baseline: 1.3938x; 1.3938x over previous
#include <cuda_runtime.h>
#include <math.h>

#define Nn 8192
#define Dd 4
#define Ff 256
#define Hh 512
#define Aa 64
#define Ee (Nn*Dd)
#define G4 2048
#define NCTA 32   /* CTAs per direction */
#define FLAGN (NCTA*4)  /* 4 warp-releases per CTA */
#define ZG 16     /* floats per z group slot (4 data + 12 pad = 64B stride) */
#define CPAD 32   /* ints per counter slot: own 128B line */

// ---------------- device scratch (no cudaMalloc allowed) ----------------
__device__ float g_preF[(size_t)Ee*G4];           // edges @ Wih_f^T + b_f
__device__ float g_preB[(size_t)Ee*G4];           // edges @ Wih_b^T + b_b
__device__ float g_arcA[(size_t)Ee*Hh];           // fwd arc_h (== ef, edge layout)
__device__ float g_arcB[(size_t)Ee*Hh];           // bwd arc_h at [node][slot]
__device__ float g_z  [2][(size_t)Nn*64*ZG];      // z accumulators, v4 groups
__device__ float g_hid[(size_t)Ee*Hh];            // decoder hidden
__device__ int   g_cz[2][(size_t)Nn*CPAD];

// ---------------- helpers ----------------
__device__ __forceinline__ int ld_acq(const int* p){
    int v; asm volatile("ld.acquire.gpu.b32 %0,[%1];":"=r"(v):"l"(p):"memory"); return v;
}
__device__ __forceinline__ void red_rel(int* p){
    asm volatile("red.release.gpu.global.add.s32 [%0], 1;"::"l"(p):"memory");
}
__device__ __forceinline__ void red_v4(float* p, float a, float b, float c, float d){
    asm volatile("red.global.v4.f32.add [%0], {%1, %2, %3, %4};"
                 ::"l"(p),"f"(a),"f"(b),"f"(c),"f"(d):"memory");
}
__device__ __forceinline__ float fsig(float x){ return 1.f/(1.f+__expf(-x)); }
__device__ __forceinline__ float ftanh(float x){
    float e = __expf(-2.f*fabsf(x));
    float t = (1.f-e)/(1.f+e);
    return copysignf(t, x);
}
__device__ __forceinline__ void ffma2(unsigned long long& acc,
                                      unsigned long long a, unsigned long long b){
    asm("fma.rn.f32x2 %0, %1, %2, %0;" : "+l"(acc) : "l"(a), "l"(b));
}
__device__ __forceinline__ unsigned long long packf2(float lo, float hi){
    unsigned long long v;
    asm("mov.b64 %0, {%1, %2};" : "=l"(v) : "f"(lo), "f"(hi));
    return v;
}

// z slot address: node i, arc d, unit a  ->  i*1024 + (d*16 + a/4)*ZG + (a%4)
__device__ __forceinline__ size_t zaddr(int i, int d, int a){
    return (size_t)i*(64*ZG) + (size_t)(d*16 + (a>>2))*ZG + (a&3);
}

// ---------------- init: counters + z-seed (ba + x[:3] @ Wa[:,512:515]^T) ---
__global__ void init_kernel(const float* __restrict__ edges,
                            const float* __restrict__ Wa,
                            const float* __restrict__ ba)
{
    int idx = blockIdx.x*256 + threadIdx.x;        // 0 .. 2^22-1
    if (idx < Nn*CPAD){
        g_cz[0][idx]=0; g_cz[1][idx]=0;
    }
    int dir = idx >> 21;
    int rem = idx & ((1<<21)-1);
    int i = rem >> 8;
    int d = (rem >> 6) & 3;
    int a = rem & 63;
    float z = ba[a];
    size_t e = 0; bool ok = true;
    if (dir == 0) e = (size_t)i*4 + d;
    else { int cn = i+1+d; if (cn < Nn) e = (size_t)cn*4 + d; else ok = false; }
    if (ok){
        const float* x  = edges + e*Ff;
        const float* wr = Wa + (size_t)a*(Hh+3) + Hh;
        z += x[0]*wr[0] + x[1]*wr[1] + x[2]*wr[2];
    }
    g_z[dir][zaddr(i, d, a)] = z;
}

// ------------- SGEMM: C[M,Nc] = A[M,K] @ B[Nc,K]^T + bias (opt relu) -------
// mode 0: plain A.  mode 1: A rows are feat[e] = [ef[e] | eb[e]] gathered.
// Inner loop uses fma.rn.f32x2 (2 fp32 FMA per issue slot).
__global__ void __launch_bounds__(256) gemm_kernel(
    const float* __restrict__ A, const float* __restrict__ B,
    const float* __restrict__ bias, float* __restrict__ C,
    int M, int Nc, int K, int mode)
{
    __shared__ float sA[16][132];
    __shared__ float sB[16][132];
    int tid = threadIdx.x;
    int n0 = blockIdx.x * 128;
    int m0 = blockIdx.y * 128;
    int tx = tid & 15, ty = tid >> 4;
    unsigned long long accp[8][4];
    #pragma unroll
    for (int ii=0; ii<8; ii++)
        #pragma unroll
        for (int jj=0; jj<4; jj++) accp[ii][jj] = 0ull;

    for (int k0 = 0; k0 < K; k0 += 16){
        #pragma unroll
        for (int u = 0; u < 2; u++){
            int v = tid + u*256;
            int row = v >> 2, kq = v & 3;
            float4 va;
            if (mode == 0){
                va = *(const float4*)(A + (size_t)(m0+row)*K + k0 + kq*4);
            } else {
                int e = m0 + row;
                int kk = k0 + kq*4;
                if (kk < Hh){
                    va = *(const float4*)(g_arcA + (size_t)e*Hh + kk);
                } else {
                    int d = e & 3, j = e >> 2;
                    if (j >= 1+d)
                        va = *(const float4*)(g_arcB + (size_t)(e - 4*(1+d))*Hh + (kk - Hh));
                    else
                        va = make_float4(0.f,0.f,0.f,0.f);
                }
            }
            sA[kq*4+0][row]=va.x; sA[kq*4+1][row]=va.y;
            sA[kq*4+2][row]=va.z; sA[kq*4+3][row]=va.w;
            float4 vb = *(const float4*)(B + (size_t)(n0+row)*K + k0 + kq*4);
            sB[kq*4+0][row]=vb.x; sB[kq*4+1][row]=vb.y;
            sB[kq*4+2][row]=vb.z; sB[kq*4+3][row]=vb.w;
        }
        __syncthreads();
        #pragma unroll
        for (int k=0; k<16; k++){
            float4 a0 = *(const float4*)&sA[k][ty*8];
            float4 a1 = *(const float4*)&sA[k][ty*8+4];
            float4 b0 = *(const float4*)&sB[k][tx*8];
            float4 b1 = *(const float4*)&sB[k][tx*8+4];
            unsigned long long bp[4] = {
                packf2(b0.x,b0.y), packf2(b0.z,b0.w),
                packf2(b1.x,b1.y), packf2(b1.z,b1.w)
            };
            float av[8] = {a0.x,a0.y,a0.z,a0.w,a1.x,a1.y,a1.z,a1.w};
            #pragma unroll
            for (int ii=0; ii<8; ii++){
                unsigned long long ap = packf2(av[ii], av[ii]);
                #pragma unroll
                for (int jj=0; jj<4; jj++)
                    ffma2(accp[ii][jj], ap, bp[jj]);
            }
        }
        __syncthreads();
    }
    #pragma unroll
    for (int ii=0; ii<8; ii++){
        int m = m0 + ty*8 + ii;
        #pragma unroll
        for (int jj=0; jj<4; jj++){
            int n = n0 + tx*8 + jj*2;
            float lo = __uint_as_float((unsigned)accp[ii][jj]);
            float hi = __uint_as_float((unsigned)(accp[ii][jj] >> 32));
            float v0 = lo + bias[n];
            float v1 = hi + bias[n+1];
            if (mode == 1){ v0 = fmaxf(v0, 0.f); v1 = fmaxf(v1, 0.f); }
            C[(size_t)m*Nc + n]     = v0;
            C[(size_t)m*Nc + n + 1] = v1;
        }
    }
}

// ---------------- persistent bidirectional recurrence ----------------------
// 32 CTAs x 512 threads per direction. CTA ct owns h-dims [ct*16, ct*16+16).
// Warp-local head: warp d does arc d's cell (lanes 0..15) + that arc's 64
// z-dots via shuffles + its own release (flag full at 128). 4 syncs/step.
__global__ void __launch_bounds__(512, 1) recur_kernel(
    const float* __restrict__ Whh_f, const float* __restrict__ Whh_b,
    const float* __restrict__ Wa, const float* __restrict__ Wao,
    const float* __restrict__ bao)
{
    const int dir = blockIdx.x >> 5;
    const int ct  = blockIdx.x & 31;
    const int tid = threadIdx.x;
    const int w = tid >> 5, l = tid & 31;

    const float* Whh = dir ? Whh_b : Whh_f;
    const float* preX = dir ? g_preB : g_preF;
    float* arc  = dir ? g_arcB : g_arcA;
    float* zArr = g_z[dir];
    int* cz = g_cz[dir];

    __shared__ float sWa[16][64];
    __shared__ float sWao[64];
    __shared__ float sbao;
    __shared__ float carc_s[4][16];
    __shared__ float logit_s[4];
    __shared__ __align__(16) float hn_s[512];
    __shared__ float u_ring[4][64];   // [node&3][g*16+q]
    __shared__ float c_ring[4][16];   // [node&3][q]

    for (int x = tid; x < 16*64; x += 512){
        int q = x >> 6, a = x & 63;
        sWa[q][a] = Wa[(size_t)a*(Hh+3) + ct*16 + q];
    }
    if (tid < 64) sWao[tid] = Wao[tid];
    if (tid == 0) sbao = bao[0];

    // weights: thread -> local row r=tid>>3 (gate g=r>>4, dim q=r&15),
    // column quads (m*8+sub)*4, m=0..15 (conflict-free LDS.128 interleave)
    const int r   = tid >> 3;
    const int sub = tid & 7;
    const int rowG = (r >> 4)*Hh + ct*16 + (r & 15);
    ulonglong2 wq[16];
    #pragma unroll
    for (int m=0; m<16; m++){
        float4 v = *(const float4*)(Whh + (size_t)rowG*Hh + (m*8 + sub)*4);
        wq[m] = *(ulonglong2*)&v;
    }
    __syncthreads();

    // cell mapping: warp w (w<4) handles arc d=w; lanes 0..15 do the cell
    const int qA = l & 15;
    const int jj = ct*16 + qA;

    // prefetch pre for t=0
    float pg[4] = {0.f,0.f,0.f,0.f};
    if (w < 4 && l < 16){
        int i0 = dir ? Nn-1 : 0;
        bool v0 = dir ? (i0+1+w < Nn) : (i0-1-w >= 0);
        if (v0){
            size_t e = dir ? ((size_t)(i0+1+w)*4 + w) : ((size_t)i0*4 + w);
            const float* pr = preX + e*G4;
            pg[0]=__ldg(pr+jj); pg[1]=__ldg(pr+Hh+jj);
            pg[2]=__ldg(pr+2*Hh+jj); pg[3]=__ldg(pr+3*Hh+jj);
        }
    }

    for (int t = 0; t < Nn; t++){
        const int i = dir ? (Nn-1-t) : t;

        // ==== HEAD (warps 0..3): cell + z-dots + per-warp release ========
        if (w < 4){
            const int d = w;
            float ha = 0.f, ca = 0.f;
            if (l < 16){
                bool valid = dir ? (i+1+d < Nn) : (i-1-d >= 0);
                if (valid){
                    int p  = dir ? (i+1+d) : (i-1-d);
                    int ps = p & 3;
                    float gi = pg[0] + u_ring[ps][qA];
                    float gf = pg[1] + u_ring[ps][16 + qA];
                    float gg = pg[2] + u_ring[ps][32 + qA];
                    float go = pg[3] + u_ring[ps][48 + qA];
                    float cp = c_ring[ps][qA];
                    ca = fsig(gf)*cp + fsig(gi)*ftanh(gg);
                    ha = fsig(go)*ftanh(ca);
                }
                carc_s[d][qA] = ca;
                __stcg(arc + ((size_t)i*4 + d)*Hh + jj, ha);
            }
            // z-dots for arc d: lane l covers units a = 2l, 2l+1
            float zv0 = 0.f, zv1 = 0.f;
            const int a0 = 2*l;
            #pragma unroll
            for (int q2=0; q2<16; q2++){
                float hq = __shfl_sync(0xffffffffu, ha, q2);
                zv0 = fmaf(sWa[q2][a0],     hq, zv0);
                zv1 = fmaf(sWa[q2][a0 + 1], hq, zv1);
            }
            float n0 = __shfl_down_sync(0xffffffffu, zv0, 1);
            float n1 = __shfl_down_sync(0xffffffffu, zv1, 1);
            if ((l & 1) == 0)
                red_v4(&zArr[(size_t)i*(64*ZG) + (size_t)(d*16 + (l>>1))*ZG],
                       zv0, zv1, n0, n1);
            __syncwarp();
            if (l == 0) red_rel(&cz[(size_t)i*CPAD]);

            // prefetch next step's pre (after release, hidden under barrier)
            if (l < 16){
                pg[0]=pg[1]=pg[2]=pg[3]=0.f;
                if (t+1 < Nn){
                    int i2 = dir ? (i-1) : (i+1);
                    bool v2 = dir ? (i2+1+d < Nn) : (i2-1-d >= 0);
                    if (v2){
                        size_t e = dir ? ((size_t)(i2+1+d)*4 + d) : ((size_t)i2*4 + d);
                        const float* pr = preX + e*G4;
                        pg[0]=__ldg(pr+jj); pg[1]=__ldg(pr+Hh+jj);
                        pg[2]=__ldg(pr+2*Hh+jj); pg[3]=__ldg(pr+3*Hh+jj);
                    }
                }
            }
        }
        if (tid == 0){
            while (ld_acq(&cz[(size_t)i*CPAD]) < FLAGN) {}
        }
        __syncthreads();   // S1: barrier observed

        // ==== POST: arc loads (independent), then logits ================
        float av[4];
        #pragma unroll
        for (int d=0; d<4; d++)
            av[d] = __ldcg(arc + ((size_t)i*4 + d)*Hh + tid);
        if (w < 4){
            float z1 = __ldcg(&zArr[zaddr(i, w, l)]);
            float z2 = __ldcg(&zArr[zaddr(i, w, l + 32)]);
            float s = fmaxf(z1, 0.f)*sWao[l] + fmaxf(z2, 0.f)*sWao[l + 32];
            #pragma unroll
            for (int off=16; off; off >>= 1) s += __shfl_xor_sync(0xffffffffu, s, off);
            if (l == 0) logit_s[w] = ftanh(s + sbao);
        }
        __syncthreads();   // S2: logits ready

        // ---- softmax weights (redundant per thread) ---------------------
        float wgt[4];
        {
            bool vld[4]; float m = -1e30f; int nv = 0;
            #pragma unroll
            for (int d=0; d<4; d++){
                vld[d] = dir ? (i+1+d < Nn) : (i-1-d >= 0);
                if (vld[d]){ m = fmaxf(m, logit_s[d]); nv++; }
            }
            float ssum = 0.f;
            #pragma unroll
            for (int d=0; d<4; d++){
                float ev = vld[d] ? __expf(logit_s[d]-m) : 0.f;
                wgt[d] = ev; ssum += ev;
            }
            if (nv){
                float inv = 1.f/ssum;
                #pragma unroll
                for (int d=0; d<4; d++) wgt[d] *= inv;
            }
        }

        // ---- h_node into smem; c_node into local ring -------------------
        {
            float h0 = 0.f;
            #pragma unroll
            for (int d=0; d<4; d++) h0 = fmaf(wgt[d], av[d], h0);
            hn_s[tid] = h0;
        }
        if (tid < 16){
            float c = 0.f;
            #pragma unroll
            for (int d=0; d<4; d++) c = fmaf(wgt[d], carc_s[d][tid], c);
            c_ring[i & 3][tid] = c;
        }
        __syncthreads();   // S3: hn_s ready

        // ---- u rows = Whh_rows @ h_node, f32x2 + LDS.128 ----------------
        {
            unsigned long long acc0 = 0ull, acc1 = 0ull;
            const ulonglong2* hv4 = (const ulonglong2*)hn_s;
            #pragma unroll
            for (int m=0; m<16; m++){
                ulonglong2 hq = hv4[m*8 + sub];
                ffma2(acc0, wq[m].x, hq.x);
                ffma2(acc1, wq[m].y, hq.y);
            }
            float s = __uint_as_float((unsigned)acc0)
                    + __uint_as_float((unsigned)(acc0 >> 32))
                    + __uint_as_float((unsigned)acc1)
                    + __uint_as_float((unsigned)(acc1 >> 32));
            s += __shfl_xor_sync(0xffffffffu, s, 1);
            s += __shfl_xor_sync(0xffffffffu, s, 2);
            s += __shfl_xor_sync(0xffffffffu, s, 4);
            if (sub == 0) u_ring[i & 3][r] = s;
        }
        __syncthreads();   // S4: ring visible before next step's cell
    }
}

// ---------------- final: out[e] = hid[e] . Wdo + bdo --------------------
__global__ void final_kernel(const float* __restrict__ Wdo,
                             const float* __restrict__ bdo,
                             float* __restrict__ out)
{
    int gw = (blockIdx.x*blockDim.x + threadIdx.x) >> 5;
    int l = threadIdx.x & 31;
    if (gw >= Ee) return;
    const float* h = g_hid + (size_t)gw*Hh;
    float s = 0.f;
    #pragma unroll
    for (int q=0; q<16; q++) s = fmaf(h[l + q*32], Wdo[l + q*32], s);
    #pragma unroll
    for (int off=16; off; off >>= 1) s += __shfl_xor_sync(0xffffffffu, s, off);
    if (l == 0) out[gw] = s + bdo[0];
}

// ---------------- launch --------------------------------------------------
extern "C" void kernel_launch(void* const* d_in, const int* in_sizes, int n_in,
                              void* d_out, int out_size)
{
    const float* edges = (const float*)d_in[0];
    const float* Wih_f = (const float*)d_in[1];
    const float* Whh_f = (const float*)d_in[2];
    const float* b_f   = (const float*)d_in[3];
    const float* Wih_b = (const float*)d_in[4];
    const float* Whh_b = (const float*)d_in[5];
    const float* b_b   = (const float*)d_in[6];
    const float* Wa    = (const float*)d_in[7];
    const float* ba    = (const float*)d_in[8];
    const float* Wao   = (const float*)d_in[9];
    const float* bao   = (const float*)d_in[10];
    const float* Wd    = (const float*)d_in[11];
    const float* bd    = (const float*)d_in[12];
    const float* Wdo   = (const float*)d_in[13];
    const float* bdo   = (const float*)d_in[14];
    float* out = (float*)d_out;

    float *preF, *preB, *hid;
    cudaGetSymbolAddress((void**)&preF, g_preF);
    cudaGetSymbolAddress((void**)&preB, g_preB);
    cudaGetSymbolAddress((void**)&hid,  g_hid);

    // 1. counters + z seed
    init_kernel<<<16384, 256>>>(edges, Wa, ba);
    // 2. input-side GEMMs: pre = edges @ Wih^T + b
    gemm_kernel<<<dim3(G4/128, Ee/128), 256>>>(edges, Wih_f, b_f, preF, Ee, G4, Ff, 0);
    gemm_kernel<<<dim3(G4/128, Ee/128), 256>>>(edges, Wih_b, b_b, preB, Ee, G4, Ff, 0);
    // 3. bidirectional recurrence (persistent, 64 CTAs, one sync per step)
    recur_kernel<<<2*NCTA, 512>>>(Whh_f, Whh_b, Wa, Wao, bao);
    // 4. decoder GEMM: hid = relu(feat @ Wd^T + bd), feat gathered from arcs
    gemm_kernel<<<dim3(Hh/128, Ee/128), 256>>>(nullptr, Wd, bd, hid, Ee, Hh, 2*Hh, 1);
    // 5. output projection
    final_kernel<<<(Ee*32)/256, 256>>>(Wdo, bdo, out);
}

// round 17
// speedup vs baseline: 1.5165x; 1.0880x over previous
#include <cuda_runtime.h>
#include <math.h>

#define Nn 8192
#define Dd 4
#define Ff 256
#define Hh 512
#define Aa 64
#define Ee (Nn*Dd)
#define G4 2048
#define NCTA 32         /* CTAs per direction */
#define FLAGN (NCTA*4)  /* 4 warp-releases per CTA per node */
#define ZG 16           /* floats per z group slot (4 data + 12 pad) */
#define CPAD 32         /* ints per counter slot: own 128B line */

// ---------------- device scratch (no cudaMalloc allowed) ----------------
__device__ float g_preF[(size_t)Ee*G4];           // edges @ Wih_f^T + b_f
__device__ float g_preB[(size_t)Ee*G4];           // edges @ Wih_b^T + b_b
__device__ float g_arcA[(size_t)Ee*Hh];           // fwd arc_h (== ef, edge layout)
__device__ float g_arcB[(size_t)Ee*Hh];           // bwd arc_h at [node][slot]
__device__ float g_z  [2][(size_t)Nn*64*ZG];      // z accumulators, v4 groups
__device__ float g_hid[(size_t)Ee*Hh];            // decoder hidden
__device__ int   g_cz[2][(size_t)Nn*CPAD];

// ---------------- helpers ----------------
__device__ __forceinline__ int ld_acq(const int* p){
    int v; asm volatile("ld.acquire.gpu.b32 %0,[%1];":"=r"(v):"l"(p):"memory"); return v;
}
__device__ __forceinline__ void red_rel(int* p){
    asm volatile("red.release.gpu.global.add.s32 [%0], 1;"::"l"(p):"memory");
}
__device__ __forceinline__ void red_v4(float* p, float a, float b, float c, float d){
    asm volatile("red.global.v4.f32.add [%0], {%1, %2, %3, %4};"
                 ::"l"(p),"f"(a),"f"(b),"f"(c),"f"(d):"memory");
}
__device__ __forceinline__ float fsig(float x){ return 1.f/(1.f+__expf(-x)); }
__device__ __forceinline__ float ftanh(float x){
    float e = __expf(-2.f*fabsf(x));
    float t = (1.f-e)/(1.f+e);
    return copysignf(t, x);
}
__device__ __forceinline__ void ffma2(unsigned long long& acc,
                                      unsigned long long a, unsigned long long b){
    asm("fma.rn.f32x2 %0, %1, %2, %0;" : "+l"(acc) : "l"(a), "l"(b));
}
__device__ __forceinline__ unsigned long long packf2(float lo, float hi){
    unsigned long long v;
    asm("mov.b64 %0, {%1, %2};" : "=l"(v) : "f"(lo), "f"(hi));
    return v;
}

// z slot address: node i, arc d, unit a  ->  i*1024 + (d*16 + a/4)*ZG + (a%4)
__device__ __forceinline__ size_t zaddr(int i, int d, int a){
    return (size_t)i*(64*ZG) + (size_t)(d*16 + (a>>2))*ZG + (a&3);
}

// ---------------- init: counters + z-seed (ba + x[:3] @ Wa[:,512:515]^T) ---
__global__ void init_kernel(const float* __restrict__ edges,
                            const float* __restrict__ Wa,
                            const float* __restrict__ ba)
{
    int idx = blockIdx.x*256 + threadIdx.x;        // 0 .. 2^22-1
    if (idx < Nn*CPAD){
        g_cz[0][idx]=0; g_cz[1][idx]=0;
    }
    int dir = idx >> 21;
    int rem = idx & ((1<<21)-1);
    int i = rem >> 8;
    int d = (rem >> 6) & 3;
    int a = rem & 63;
    float z = ba[a];
    size_t e = 0; bool ok = true;
    if (dir == 0) e = (size_t)i*4 + d;
    else { int cn = i+1+d; if (cn < Nn) e = (size_t)cn*4 + d; else ok = false; }
    if (ok){
        const float* x  = edges + e*Ff;
        const float* wr = Wa + (size_t)a*(Hh+3) + Hh;
        z += x[0]*wr[0] + x[1]*wr[1] + x[2]*wr[2];
    }
    g_z[dir][zaddr(i, d, a)] = z;
}

// ------------- SGEMM: C[M,Nc] = A[M,K] @ B[Nc,K]^T + bias (opt relu) -------
// mode 0: plain A.  mode 1: A rows are feat[e] = [ef[e] | eb[e]] gathered.
__global__ void __launch_bounds__(256) gemm_kernel(
    const float* __restrict__ A, const float* __restrict__ B,
    const float* __restrict__ bias, float* __restrict__ C,
    int M, int Nc, int K, int mode)
{
    __shared__ float sA[16][132];
    __shared__ float sB[16][132];
    int tid = threadIdx.x;
    int n0 = blockIdx.x * 128;
    int m0 = blockIdx.y * 128;
    int tx = tid & 15, ty = tid >> 4;
    unsigned long long accp[8][4];
    #pragma unroll
    for (int ii=0; ii<8; ii++)
        #pragma unroll
        for (int jj=0; jj<4; jj++) accp[ii][jj] = 0ull;

    for (int k0 = 0; k0 < K; k0 += 16){
        #pragma unroll
        for (int u = 0; u < 2; u++){
            int v = tid + u*256;
            int row = v >> 2, kq = v & 3;
            float4 va;
            if (mode == 0){
                va = *(const float4*)(A + (size_t)(m0+row)*K + k0 + kq*4);
            } else {
                int e = m0 + row;
                int kk = k0 + kq*4;
                if (kk < Hh){
                    va = *(const float4*)(g_arcA + (size_t)e*Hh + kk);
                } else {
                    int d = e & 3, j = e >> 2;
                    if (j >= 1+d)
                        va = *(const float4*)(g_arcB + (size_t)(e - 4*(1+d))*Hh + (kk - Hh));
                    else
                        va = make_float4(0.f,0.f,0.f,0.f);
                }
            }
            sA[kq*4+0][row]=va.x; sA[kq*4+1][row]=va.y;
            sA[kq*4+2][row]=va.z; sA[kq*4+3][row]=va.w;
            float4 vb = *(const float4*)(B + (size_t)(n0+row)*K + k0 + kq*4);
            sB[kq*4+0][row]=vb.x; sB[kq*4+1][row]=vb.y;
            sB[kq*4+2][row]=vb.z; sB[kq*4+3][row]=vb.w;
        }
        __syncthreads();
        #pragma unroll
        for (int k=0; k<16; k++){
            float4 a0 = *(const float4*)&sA[k][ty*8];
            float4 a1 = *(const float4*)&sA[k][ty*8+4];
            float4 b0 = *(const float4*)&sB[k][tx*8];
            float4 b1 = *(const float4*)&sB[k][tx*8+4];
            unsigned long long bp[4] = {
                packf2(b0.x,b0.y), packf2(b0.z,b0.w),
                packf2(b1.x,b1.y), packf2(b1.z,b1.w)
            };
            float av[8] = {a0.x,a0.y,a0.z,a0.w,a1.x,a1.y,a1.z,a1.w};
            #pragma unroll
            for (int ii=0; ii<8; ii++){
                unsigned long long ap = packf2(av[ii], av[ii]);
                #pragma unroll
                for (int jj=0; jj<4; jj++)
                    ffma2(accp[ii][jj], ap, bp[jj]);
            }
        }
        __syncthreads();
    }
    #pragma unroll
    for (int ii=0; ii<8; ii++){
        int m = m0 + ty*8 + ii;
        #pragma unroll
        for (int jj=0; jj<4; jj++){
            int n = n0 + tx*8 + jj*2;
            float lo = __uint_as_float((unsigned)accp[ii][jj]);
            float hi = __uint_as_float((unsigned)(accp[ii][jj] >> 32));
            float v0 = lo + bias[n];
            float v1 = hi + bias[n+1];
            if (mode == 1){ v0 = fmaxf(v0, 0.f); v1 = fmaxf(v1, 0.f); }
            C[(size_t)m*Nc + n]     = v0;
            C[(size_t)m*Nc + n + 1] = v1;
        }
    }
}

// ---------------- warp-specialized pipelined recurrence --------------------
// 32 CTAs x 512 thr per direction. CTA ct owns dims [ct*16, ct*16+16).
// HEAD (warps 0-7): critical chain for node t (+ d0 cell of node t+1).
// HELPERS (warps 8-10): node t+1's d1..3 cells/REDs/releases, one step ahead.
// Warp 11: smem prefetch of pre-gate values for node t+2.
// Flag[node] full at 128 arrivals (4 warp-releases x 32 CTAs).
__global__ void __launch_bounds__(512, 1) recur_kernel(
    const float* __restrict__ Whh_f, const float* __restrict__ Whh_b,
    const float* __restrict__ Wa, const float* __restrict__ Wao,
    const float* __restrict__ bao)
{
    const int dir = blockIdx.x >> 5;
    const int ct  = blockIdx.x & 31;
    const int tid = threadIdx.x;
    const int w = tid >> 5, l = tid & 31;

    const float* Whh = dir ? Whh_b : Whh_f;
    const float* preX = dir ? g_preB : g_preF;
    float* arc  = dir ? g_arcB : g_arcA;
    float* zArr = g_z[dir];
    int* cz = g_cz[dir];

    __shared__ float sWa[16][64];
    __shared__ float sWao[64];
    __shared__ float sbao;
    __shared__ float carcbuf[2][3][16];       // helpers' c_arc d1..3, parity
    __shared__ float logit_s[4];
    __shared__ __align__(16) float hn_s[512];
    __shared__ float u_ring[4][64];           // [step&3][g*16+q]
    __shared__ float c_ring[4][16];           // [step&3][q]
    __shared__ float prebuf[4][4][4][16];     // [slot][arc][gate][dim]

    for (int x = tid; x < 16*64; x += 512){
        int q = x >> 6, a = x & 63;
        sWa[q][a] = Wa[(size_t)a*(Hh+3) + ct*16 + q];
    }
    if (tid < 64) sWao[tid] = Wao[tid];
    if (tid == 0) sbao = bao[0];

    // matvec weights (all 512 threads): row r=tid>>3, quads (m*8+sub)*4
    const int r   = tid >> 3;
    const int sub = tid & 7;
    const int rowG = (r >> 4)*Hh + ct*16 + (r & 15);
    ulonglong2 wq[16];
    #pragma unroll
    for (int m=0; m<16; m++){
        float4 v = *(const float4*)(Whh + (size_t)rowG*Hh + (m*8 + sub)*4);
        wq[m] = *(ulonglong2*)&v;
    }

    const int node0 = dir ? Nn-1 : 0;

    // ---- prologue: node_0 arcs are all zeros; prebuf slot 1 for node_1 ----
    if (tid < 64){
        int d = tid >> 4, q = tid & 15;
        __stcg(arc + ((size_t)node0*4 + d)*Hh + ct*16 + q, 0.f);
    }
    if (tid >= 64 && tid < 112){
        int v = tid - 64;
        carcbuf[0][v >> 4][v & 15] = 0.f;
    }
    if (tid >= 128 && tid < 384){
        int v = tid - 128;
        int d = v >> 6, g = (v >> 4) & 3, q = v & 15;
        int n1 = dir ? Nn-2 : 1;
        size_t e;
        if (dir == 0) e = (size_t)n1*4 + d;
        else { int cn = n1+1+d; if (cn > Nn-1) cn = Nn-1; e = (size_t)cn*4 + d; }
        prebuf[1][d][g][q] = __ldg(preX + e*G4 + (size_t)g*Hh + ct*16 + q);
    }
    float d0carc = 0.f;      // warp0 lanes 0..15: c_arc of d0 for node_t
    __syncthreads();
    if (tid == 0 || tid == 256 || tid == 288 || tid == 320)
        red_rel(&cz[(size_t)node0*CPAD]);

    float wgt[4];

    for (int t = 0; t < Nn; t++){
        const int i  = dir ? (Nn-1-t) : t;          // node_t
        const int i1 = dir ? (i-1) : (i+1);         // node_{t+1}
        const bool hav1 = (t+1 < Nn);

        if (tid < 256){
            // ================= HEAD =================
            if (tid == 0){
                while (ld_acq(&cz[(size_t)i*CPAD]) < FLAGN) {}
            }
            asm volatile("bar.sync 1, 256;" ::: "memory");
            // arc loads (2 dims per thread) + logits (warps 0..3)
            float2 av2[4];
            #pragma unroll
            for (int d=0; d<4; d++)
                av2[d] = __ldcg((const float2*)(arc + ((size_t)i*4 + d)*Hh) + tid);
            if (w < 4){
                float z1 = __ldcg(&zArr[zaddr(i, w, l)]);
                float z2 = __ldcg(&zArr[zaddr(i, w, l + 32)]);
                float s = fmaxf(z1, 0.f)*sWao[l] + fmaxf(z2, 0.f)*sWao[l + 32];
                #pragma unroll
                for (int off=16; off; off >>= 1)
                    s += __shfl_xor_sync(0xffffffffu, s, off);
                if (l == 0) logit_s[w] = ftanh(s + sbao);
            }
            asm volatile("bar.sync 1, 256;" ::: "memory");
            // softmax (validity: node_t arc d valid iff t > d)
            {
                float ssum = 0.f;
                #pragma unroll
                for (int d=0; d<4; d++){
                    float ev = (t > d) ? __expf(logit_s[d]) : 0.f;
                    wgt[d] = ev; ssum += ev;
                }
                if (t > 0){
                    float inv = 1.f/ssum;
                    #pragma unroll
                    for (int d=0; d<4; d++) wgt[d] *= inv;
                }
            }
            // h_node (2 dims per thread)
            {
                float h0 = 0.f, h1 = 0.f;
                #pragma unroll
                for (int d=0; d<4; d++){
                    h0 = fmaf(wgt[d], av2[d].x, h0);
                    h1 = fmaf(wgt[d], av2[d].y, h1);
                }
                ((float2*)hn_s)[tid] = make_float2(h0, h1);
            }
            // c_node (threads 0..15 hold d0carc; d1..3 from helpers' buffer)
            if (tid < 16){
                float c = wgt[0]*d0carc;
                #pragma unroll
                for (int d=1; d<4; d++)
                    c = fmaf(wgt[d], carcbuf[t & 1][d-1][tid], c);
                c_ring[t & 3][tid] = c;
            }
        } else {
            // ================= HELPERS (one step ahead) =================
            if (hav1){
                if (w >= 8 && w <= 10){
                    const int d = w - 7;              // arc 1..3 of node_{t+1}
                    float ha = 0.f, ca = 0.f;
                    if (l < 16){
                        if (t >= d){                  // node_{t+1} arc d valid
                            int ps = (t - d) & 3;
                            float gi = prebuf[(t+1)&3][d][0][l] + u_ring[ps][l];
                            float gf = prebuf[(t+1)&3][d][1][l] + u_ring[ps][16+l];
                            float gg = prebuf[(t+1)&3][d][2][l] + u_ring[ps][32+l];
                            float go = prebuf[(t+1)&3][d][3][l] + u_ring[ps][48+l];
                            float cp = c_ring[ps][l];
                            ca = fsig(gf)*cp + fsig(gi)*ftanh(gg);
                            ha = fsig(go)*ftanh(ca);
                        }
                        carcbuf[(t+1) & 1][d-1][l] = ca;
                        __stcg(arc + ((size_t)i1*4 + d)*Hh + ct*16 + l, ha);
                    }
                    // z-dots for this arc (lane l covers units 2l, 2l+1)
                    float zv0 = 0.f, zv1 = 0.f;
                    const int a0 = 2*l;
                    #pragma unroll
                    for (int q2=0; q2<16; q2++){
                        float hq = __shfl_sync(0xffffffffu, ha, q2);
                        zv0 = fmaf(sWa[q2][a0],     hq, zv0);
                        zv1 = fmaf(sWa[q2][a0 + 1], hq, zv1);
                    }
                    float n0 = __shfl_down_sync(0xffffffffu, zv0, 1);
                    float n1 = __shfl_down_sync(0xffffffffu, zv1, 1);
                    if ((l & 1) == 0)
                        red_v4(&zArr[(size_t)i1*(64*ZG) + (size_t)(d*16 + (l>>1))*ZG],
                               zv0, zv1, n0, n1);
                    __syncwarp();
                    if (l == 0) red_rel(&cz[(size_t)i1*CPAD]);
                }
                if (w == 11 && t+2 < Nn){
                    int n2 = dir ? (i-2) : (i+2);     // node_{t+2}
                    #pragma unroll
                    for (int k=0; k<8; k++){
                        int v = k*32 + l;
                        int d = v >> 6, g = (v >> 4) & 3, q = v & 15;
                        size_t e;
                        if (dir == 0) e = (size_t)n2*4 + d;
                        else { int cn = n2+1+d; if (cn > Nn-1) cn = Nn-1; e = (size_t)cn*4 + d; }
                        prebuf[(t+2)&3][d][g][q] =
                            __ldg(preX + e*G4 + (size_t)g*Hh + ct*16 + q);
                    }
                }
            }
        }
        __syncthreads();   // S2: hn_s ready; helpers done with old u/c slots

        // ---- u = Whh_rows @ h_node (all 512 threads, f32x2 + LDS.128) ----
        {
            unsigned long long acc0 = 0ull, acc1 = 0ull;
            const ulonglong2* hv4 = (const ulonglong2*)hn_s;
            #pragma unroll
            for (int m=0; m<16; m++){
                ulonglong2 hq = hv4[m*8 + sub];
                ffma2(acc0, wq[m].x, hq.x);
                ffma2(acc1, wq[m].y, hq.y);
            }
            float s = __uint_as_float((unsigned)acc0)
                    + __uint_as_float((unsigned)(acc0 >> 32))
                    + __uint_as_float((unsigned)acc1)
                    + __uint_as_float((unsigned)(acc1 >> 32));
            s += __shfl_xor_sync(0xffffffffu, s, 1);
            s += __shfl_xor_sync(0xffffffffu, s, 2);
            s += __shfl_xor_sync(0xffffffffu, s, 4);
            if (sub == 0) u_ring[t & 3][r] = s;
        }
        __syncthreads();   // S3: u_ring[t&3] visible

        // ---- HEAD warp 0: d0 cell of node_{t+1} + z-RED + release -------
        if (w == 0 && hav1){
            float ha = 0.f, ca = 0.f;
            if (l < 16){
                float gi = prebuf[(t+1)&3][0][0][l] + u_ring[t & 3][l];
                float gf = prebuf[(t+1)&3][0][1][l] + u_ring[t & 3][16 + l];
                float gg = prebuf[(t+1)&3][0][2][l] + u_ring[t & 3][32 + l];
                float go = prebuf[(t+1)&3][0][3][l] + u_ring[t & 3][48 + l];
                float cp = c_ring[t & 3][l];
                ca = fsig(gf)*cp + fsig(gi)*ftanh(gg);
                ha = fsig(go)*ftanh(ca);
                d0carc = ca;
                __stcg(arc + ((size_t)i1*4 + 0)*Hh + ct*16 + l, ha);
            }
            float zv0 = 0.f, zv1 = 0.f;
            const int a0 = 2*l;
            #pragma unroll
            for (int q2=0; q2<16; q2++){
                float hq = __shfl_sync(0xffffffffu, ha, q2);
                zv0 = fmaf(sWa[q2][a0],     hq, zv0);
                zv1 = fmaf(sWa[q2][a0 + 1], hq, zv1);
            }
            float n0 = __shfl_down_sync(0xffffffffu, zv0, 1);
            float n1 = __shfl_down_sync(0xffffffffu, zv1, 1);
            if ((l & 1) == 0)
                red_v4(&zArr[(size_t)i1*(64*ZG) + (size_t)(l>>1)*ZG],
                       zv0, zv1, n0, n1);
            __syncwarp();
            if (l == 0) red_rel(&cz[(size_t)i1*CPAD]);
        }
    }
}

// ---------------- final: out[e] = hid[e] . Wdo + bdo --------------------
__global__ void final_kernel(const float* __restrict__ Wdo,
                             const float* __restrict__ bdo,
                             float* __restrict__ out)
{
    int gw = (blockIdx.x*blockDim.x + threadIdx.x) >> 5;
    int l = threadIdx.x & 31;
    if (gw >= Ee) return;
    const float* h = g_hid + (size_t)gw*Hh;
    float s = 0.f;
    #pragma unroll
    for (int q=0; q<16; q++) s = fmaf(h[l + q*32], Wdo[l + q*32], s);
    #pragma unroll
    for (int off=16; off; off >>= 1) s += __shfl_xor_sync(0xffffffffu, s, off);
    if (l == 0) out[gw] = s + bdo[0];
}

// ---------------- launch --------------------------------------------------
extern "C" void kernel_launch(void* const* d_in, const int* in_sizes, int n_in,
                              void* d_out, int out_size)
{
    const float* edges = (const float*)d_in[0];
    const float* Wih_f = (const float*)d_in[1];
    const float* Whh_f = (const float*)d_in[2];
    const float* b_f   = (const float*)d_in[3];
    const float* Wih_b = (const float*)d_in[4];
    const float* Whh_b = (const float*)d_in[5];
    const float* b_b   = (const float*)d_in[6];
    const float* Wa    = (const float*)d_in[7];
    const float* ba    = (const float*)d_in[8];
    const float* Wao   = (const float*)d_in[9];
    const float* bao   = (const float*)d_in[10];
    const float* Wd    = (const float*)d_in[11];
    const float* bd    = (const float*)d_in[12];
    const float* Wdo   = (const float*)d_in[13];
    const float* bdo   = (const float*)d_in[14];
    float* out = (float*)d_out;

    float *preF, *preB, *hid;
    cudaGetSymbolAddress((void**)&preF, g_preF);
    cudaGetSymbolAddress((void**)&preB, g_preB);
    cudaGetSymbolAddress((void**)&hid,  g_hid);

    // 1. counters + z seed
    init_kernel<<<16384, 256>>>(edges, Wa, ba);
    // 2. input-side GEMMs: pre = edges @ Wih^T + b
    gemm_kernel<<<dim3(G4/128, Ee/128), 256>>>(edges, Wih_f, b_f, preF, Ee, G4, Ff, 0);
    gemm_kernel<<<dim3(G4/128, Ee/128), 256>>>(edges, Wih_b, b_b, preB, Ee, G4, Ff, 0);
    // 3. warp-specialized pipelined recurrence (64 CTAs)
    recur_kernel<<<2*NCTA, 512>>>(Whh_f, Whh_b, Wa, Wao, bao);
    // 4. decoder GEMM: hid = relu(feat @ Wd^T + bd), feat gathered from arcs
    gemm_kernel<<<dim3(Hh/128, Ee/128), 256>>>(nullptr, Wd, bd, hid, Ee, Hh, 2*Hh, 1);
    // 5. output projection
    final_kernel<<<(Ee*32)/256, 256>>>(Wdo, bdo, out);
}